// round 1
// baseline (speedup 1.0000x reference)
#include <cuda_runtime.h>

#define FULL 0xffffffffu

// ---------------- scratch (device globals: no allocations allowed) ----------
__device__ float2 g_psi0[256];          // state after ansatz(|0>, w[0])
__device__ float  g_cosw[24];           // cos(w/2) per [layer][qubit]
__device__ float  g_sinw[24];
__device__ float  g_a1[32 * 1023];      // layer-1 relu(<Z_0>)
__device__ float  g_pool[32 * 1022];    // layer-2 max-pooled

// ---------------- statevector: 256 amps, 8 float2 per lane ------------------
// flat index i = lane*8 + m. qubit j (0..4) -> lane bit (4-j); qubit j (5..7)
// -> m bit (7-j). (axis 0 of the (2,)*8 tensor is the MSB of i.)
struct St { float2 a[8]; };

__device__ __forceinline__ float2 shxor(float2 v, int m) {
    float2 r;
    r.x = __shfl_xor_sync(FULL, v.x, m);
    r.y = __shfl_xor_sync(FULL, v.y, m);
    return r;
}

// RY = [[c,-s],[s,c]] (real)
template<int Q>
__device__ __forceinline__ void gateRY(St& st, float c, float s, int lane) {
    if constexpr (Q >= 5) {
        constexpr int bit = 1 << (7 - Q);
#pragma unroll
        for (int m = 0; m < 8; ++m) {
            if ((m & bit) == 0) {
                float2 a = st.a[m], b = st.a[m | bit];
                st.a[m]       = make_float2(c * a.x - s * b.x, c * a.y - s * b.y);
                st.a[m | bit] = make_float2(s * a.x + c * b.x, s * a.y + c * b.y);
            }
        }
    } else {
        constexpr int lm = 1 << (4 - Q);
        float sg = (lane & lm) ? s : -s;   // lo lane: c*own - s*other ; hi: c*own + s*other
#pragma unroll
        for (int m = 0; m < 8; ++m) {
            float2 o = shxor(st.a[m], lm);
            float2 a = st.a[m];
            st.a[m] = make_float2(c * a.x + sg * o.x, c * a.y + sg * o.y);
        }
    }
}

// RX = [[c,-is],[-is,c]] : both rows -> new = c*own - i*s*other (symmetric)
template<int Q>
__device__ __forceinline__ void gateRX(St& st, float c, float s, int lane) {
    if constexpr (Q >= 5) {
        constexpr int bit = 1 << (7 - Q);
#pragma unroll
        for (int m = 0; m < 8; ++m) {
            if ((m & bit) == 0) {
                float2 a = st.a[m], b = st.a[m | bit];
                st.a[m]       = make_float2(c * a.x + s * b.y, c * a.y - s * b.x);
                st.a[m | bit] = make_float2(c * b.x + s * a.y, c * b.y - s * a.x);
            }
        }
    } else {
        constexpr int lm = 1 << (4 - Q);
#pragma unroll
        for (int m = 0; m < 8; ++m) {
            float2 o = shxor(st.a[m], lm);
            float2 a = st.a[m];
            st.a[m] = make_float2(c * a.x + s * o.y, c * a.y - s * o.x);
        }
    }
}

// RZ = diag(e^{-it/2}, e^{+it/2}); bit set -> f=+s, clear -> f=-s:
//   x' = c*x - f*y ; y' = c*y + f*x
template<int Q>
__device__ __forceinline__ void gateRZ(St& st, float c, float s, int lane) {
    if constexpr (Q >= 5) {
        constexpr int bit = 1 << (7 - Q);
#pragma unroll
        for (int m = 0; m < 8; ++m) {
            float f = (m & bit) ? s : -s;
            float2 a = st.a[m];
            st.a[m] = make_float2(c * a.x - f * a.y, c * a.y + f * a.x);
        }
    } else {
        constexpr int lm = 1 << (4 - Q);
        float f = (lane & lm) ? s : -s;
#pragma unroll
        for (int m = 0; m < 8; ++m) {
            float2 a = st.a[m];
            st.a[m] = make_float2(c * a.x - f * a.y, c * a.y + f * a.x);
        }
    }
}

template<int C, int T>
__device__ __forceinline__ void cnot(St& st, int lane) {
    if constexpr (C <= 4 && T <= 4) {
        // both qubits live in lane bits: swap across lanes where control set
        constexpr int cm = 1 << (4 - C);
        constexpr int tm = 1 << (4 - T);
        bool ctrl = (lane & cm) != 0;
#pragma unroll
        for (int m = 0; m < 8; ++m) {
            float2 o = shxor(st.a[m], tm);
            if (ctrl) st.a[m] = o;
        }
    } else if constexpr (C <= 4 && T >= 5) {
        // control in lane bits, target in local index: in-lane swap if ctrl
        constexpr int cm = 1 << (4 - C);
        constexpr int tb = 1 << (7 - T);
        bool ctrl = (lane & cm) != 0;
#pragma unroll
        for (int m = 0; m < 8; ++m) {
            if ((m & tb) == 0) {
                float2 a = st.a[m], b = st.a[m | tb];
                st.a[m]      = ctrl ? b : a;
                st.a[m | tb] = ctrl ? a : b;
            }
        }
    } else {
        // both local: compile-time register permutation
        constexpr int cb = 1 << (7 - C);
        constexpr int tb = 1 << (7 - T);
#pragma unroll
        for (int m = 0; m < 8; ++m) {
            if ((m & cb) != 0 && (m & tb) == 0) {
                float2 t = st.a[m];
                st.a[m] = st.a[m | tb];
                st.a[m | tb] = t;
            }
        }
    }
}

template<int J>
__device__ __forceinline__ void ansatzStep(St& st, const float* cw, const float* sw, int lane) {
    constexpr int C = (J < 7) ? J : 0;
    constexpr int T = (J < 7) ? J + 1 : 7;
    float c = cw[J], s = sw[J];
    gateRX<J>(st, c, s, lane);
    cnot<C, T>(st, lane);
    gateRY<J>(st, c, s, lane);
    cnot<C, T>(st, lane);
    gateRZ<J>(st, c, s, lane);
}

__device__ __forceinline__ void ansatz(St& st, const float* cw, const float* sw, int lane) {
    ansatzStep<0>(st, cw, sw, lane);
    ansatzStep<1>(st, cw, sw, lane);
    ansatzStep<2>(st, cw, sw, lane);
    ansatzStep<3>(st, cw, sw, lane);
    ansatzStep<4>(st, cw, sw, lane);
    ansatzStep<5>(st, cw, sw, lane);
    ansatzStep<6>(st, cw, sw, lane);
    ansatzStep<7>(st, cw, sw, lane);
}

// ---------------- precompute: trig coeffs + psi0 (1 warp) -------------------
__global__ void precompute_kernel(const float* __restrict__ weights) {
    int lane = threadIdx.x;
    if (lane < 24) {
        const float TWO_PI = 6.28318530717958647692f;
        float w = weights[lane];
        float wm = fmodf(w, TWO_PI);
        if (wm < 0.f) wm += TWO_PI;     // match jnp.mod semantics
        g_cosw[lane] = cosf(0.5f * wm);
        g_sinw[lane] = sinf(0.5f * wm);
    }
    __syncthreads();
    St st;
#pragma unroll
    for (int m = 0; m < 8; ++m) st.a[m] = make_float2(0.f, 0.f);
    if (lane == 0) st.a[0] = make_float2(1.f, 0.f);
    ansatz(st, &g_cosw[0], &g_sinw[0], lane);
#pragma unroll
    for (int m = 0; m < 8; ++m) g_psi0[(lane << 3) | m] = st.a[m];
}

// ---------------- quanv body: one circuit per warp ---------------------------
template<int LIN, bool ALLZ>
__device__ __forceinline__ void quanv_body(const float* __restrict__ src, float* __restrict__ dst) {
    constexpr int NSEG = LIN - 1;   // (LIN + 2*1 - 4)/1 + 1
    int gw = (int)((blockIdx.x * blockDim.x + threadIdx.x) >> 5);
    int lane = threadIdx.x & 31;
    if (gw >= 32 * NSEG) return;
    int b = gw / NSEG;
    int s = gw - b * NSEG;

    // lanes 0..3 compute the 4 data-angle sin/cos, broadcast to warp
    float myc = 1.f, mys = 0.f;
    if (lane < 4) {
        int l = s + lane - 1;                       // PAD=1
        float ang = (l >= 0 && l < LIN) ? src[b * LIN + l] : 0.f;
        myc = cosf(0.5f * ang);
        mys = sinf(0.5f * ang);
    }
    float c0 = __shfl_sync(FULL, myc, 0), s0 = __shfl_sync(FULL, mys, 0);
    float c1 = __shfl_sync(FULL, myc, 1), s1 = __shfl_sync(FULL, mys, 1);
    float c2 = __shfl_sync(FULL, myc, 2), s2 = __shfl_sync(FULL, mys, 2);
    float c3 = __shfl_sync(FULL, myc, 3), s3 = __shfl_sync(FULL, mys, 3);

    St st;
#pragma unroll
    for (int m = 0; m < 8; ++m) st.a[m] = g_psi0[(lane << 3) | m];

    // data encoding: RY(ang[i]) on qubit i, i=0..3
    gateRY<0>(st, c0, s0, lane);
    gateRY<1>(st, c1, s1, lane);
    gateRY<2>(st, c2, s2, lane);
    gateRY<3>(st, c3, s3, lane);

    ansatz(st, &g_cosw[8],  &g_sinw[8],  lane);
    ansatz(st, &g_cosw[16], &g_sinw[16], lane);

    if constexpr (!ALLZ) {
        // only <Z_0> needed (layer 2 reads channel 0 only): sign = lane bit 4
        float v = 0.f;
#pragma unroll
        for (int m = 0; m < 8; ++m) { float2 a = st.a[m]; v += a.x * a.x + a.y * a.y; }
        v = (lane & 16) ? -v : v;
#pragma unroll
        for (int o = 16; o; o >>= 1) v += __shfl_xor_sync(FULL, v, o);
        if (lane == 0) dst[gw] = fmaxf(v, 0.f);
    } else {
        float vj[8];
#pragma unroll
        for (int j = 0; j < 8; ++j) vj[j] = 0.f;
#pragma unroll
        for (int m = 0; m < 8; ++m) {
            float2 a = st.a[m];
            float p = a.x * a.x + a.y * a.y;
            int idx = (lane << 3) | m;
#pragma unroll
            for (int j = 0; j < 8; ++j) vj[j] += ((idx >> (7 - j)) & 1) ? -p : p;
        }
        float best = -2.f;
#pragma unroll
        for (int j = 0; j < 8; ++j) {
            float v = vj[j];
#pragma unroll
            for (int o = 16; o; o >>= 1) v += __shfl_xor_sync(FULL, v, o);
            best = fmaxf(best, v);
        }
        // max_j relu(v_j) == relu(max_j v_j)
        if (lane == 0) dst[gw] = fmaxf(best, 0.f);
    }
}

__global__ void __launch_bounds__(256) quanv1_kernel(const float* __restrict__ x) {
    quanv_body<1024, false>(x, g_a1);
}

__global__ void __launch_bounds__(256) quanv2_kernel() {
    quanv_body<1023, true>(g_a1, g_pool);
}

// ---------------- dense: out[b] = sum_s pool[b,s]*w[s] + bias ---------------
__global__ void __launch_bounds__(256) dense_kernel(const float* __restrict__ dw,
                                                    const float* __restrict__ db,
                                                    float* __restrict__ out) {
    int b = blockIdx.x, t = threadIdx.x;
    float acc = 0.f;
    for (int s = t; s < 1022; s += 256)
        acc += g_pool[b * 1022 + s] * dw[s];
    __shared__ float sm[256];
    sm[t] = acc;
    __syncthreads();
#pragma unroll
    for (int o = 128; o; o >>= 1) {
        if (t < o) sm[t] += sm[t + o];
        __syncthreads();
    }
    if (t == 0) out[b] = sm[0] + db[0];
}

// ---------------- launch -----------------------------------------------------
extern "C" void kernel_launch(void* const* d_in, const int* in_sizes, int n_in,
                              void* d_out, int out_size) {
    const float* x       = (const float*)d_in[0];   // (32,1024,1)
    const float* weights = (const float*)d_in[1];   // (3,8)
    const float* dw      = (const float*)d_in[2];   // (1022,1)
    const float* db      = (const float*)d_in[3];   // (1,)
    float* out = (float*)d_out;                     // (32,1)

    precompute_kernel<<<1, 32>>>(weights);

    // layer 1: 32*1023 circuits, 8 warps/block
    {
        int warps = 32 * 1023;
        int blocks = (warps + 7) / 8;
        quanv1_kernel<<<blocks, 256>>>(x);
    }
    // layer 2: 32*1022 circuits
    {
        int warps = 32 * 1022;
        int blocks = (warps + 7) / 8;
        quanv2_kernel<<<blocks, 256>>>();
    }
    dense_kernel<<<32, 256>>>(dw, db, out);
}

// round 2
// speedup vs baseline: 7.6463x; 7.6463x over previous
#include <cuda_runtime.h>

#define FULL 0xffffffffu

// ---------------- scratch (device globals) ----------------------------------
__device__ float2 g_psi0[256];          // state after ansatz(|0>, w[0])
__device__ float  g_cosw[24];           // cos(w/2) per [layer][qubit]
__device__ float  g_sinw[24];
__device__ float  g_F[81 * 8];          // grid evaluations of <Z_j>
__device__ float  g_coef[8 * 81];       // trig-poly coefficients per output j
__device__ float  g_a1[32 * 1023];      // layer-1 relu(<Z_0>)

// ---------------- warp statevector simulation (precompute only) -------------
struct St { float2 a[8]; };

__device__ __forceinline__ float2 shxor(float2 v, int m) {
    float2 r;
    r.x = __shfl_xor_sync(FULL, v.x, m);
    r.y = __shfl_xor_sync(FULL, v.y, m);
    return r;
}

template<int Q>
__device__ __forceinline__ void gateRY(St& st, float c, float s, int lane) {
    if constexpr (Q >= 5) {
        constexpr int bit = 1 << (7 - Q);
#pragma unroll
        for (int m = 0; m < 8; ++m) {
            if ((m & bit) == 0) {
                float2 a = st.a[m], b = st.a[m | bit];
                st.a[m]       = make_float2(c * a.x - s * b.x, c * a.y - s * b.y);
                st.a[m | bit] = make_float2(s * a.x + c * b.x, s * a.y + c * b.y);
            }
        }
    } else {
        constexpr int lm = 1 << (4 - Q);
        float sg = (lane & lm) ? s : -s;
#pragma unroll
        for (int m = 0; m < 8; ++m) {
            float2 o = shxor(st.a[m], lm);
            float2 a = st.a[m];
            st.a[m] = make_float2(c * a.x + sg * o.x, c * a.y + sg * o.y);
        }
    }
}

template<int Q>
__device__ __forceinline__ void gateRX(St& st, float c, float s, int lane) {
    if constexpr (Q >= 5) {
        constexpr int bit = 1 << (7 - Q);
#pragma unroll
        for (int m = 0; m < 8; ++m) {
            if ((m & bit) == 0) {
                float2 a = st.a[m], b = st.a[m | bit];
                st.a[m]       = make_float2(c * a.x + s * b.y, c * a.y - s * b.x);
                st.a[m | bit] = make_float2(c * b.x + s * a.y, c * b.y - s * a.x);
            }
        }
    } else {
        constexpr int lm = 1 << (4 - Q);
#pragma unroll
        for (int m = 0; m < 8; ++m) {
            float2 o = shxor(st.a[m], lm);
            float2 a = st.a[m];
            st.a[m] = make_float2(c * a.x + s * o.y, c * a.y - s * o.x);
        }
    }
}

template<int Q>
__device__ __forceinline__ void gateRZ(St& st, float c, float s, int lane) {
    if constexpr (Q >= 5) {
        constexpr int bit = 1 << (7 - Q);
#pragma unroll
        for (int m = 0; m < 8; ++m) {
            float f = (m & bit) ? s : -s;
            float2 a = st.a[m];
            st.a[m] = make_float2(c * a.x - f * a.y, c * a.y + f * a.x);
        }
    } else {
        constexpr int lm = 1 << (4 - Q);
        float f = (lane & lm) ? s : -s;
#pragma unroll
        for (int m = 0; m < 8; ++m) {
            float2 a = st.a[m];
            st.a[m] = make_float2(c * a.x - f * a.y, c * a.y + f * a.x);
        }
    }
}

template<int C, int T>
__device__ __forceinline__ void cnot(St& st, int lane) {
    if constexpr (C <= 4 && T <= 4) {
        constexpr int cm = 1 << (4 - C);
        constexpr int tm = 1 << (4 - T);
        bool ctrl = (lane & cm) != 0;
#pragma unroll
        for (int m = 0; m < 8; ++m) {
            float2 o = shxor(st.a[m], tm);
            if (ctrl) st.a[m] = o;
        }
    } else if constexpr (C <= 4 && T >= 5) {
        constexpr int cm = 1 << (4 - C);
        constexpr int tb = 1 << (7 - T);
        bool ctrl = (lane & cm) != 0;
#pragma unroll
        for (int m = 0; m < 8; ++m) {
            if ((m & tb) == 0) {
                float2 a = st.a[m], b = st.a[m | tb];
                st.a[m]      = ctrl ? b : a;
                st.a[m | tb] = ctrl ? a : b;
            }
        }
    } else {
        constexpr int cb = 1 << (7 - C);
        constexpr int tb = 1 << (7 - T);
#pragma unroll
        for (int m = 0; m < 8; ++m) {
            if ((m & cb) != 0 && (m & tb) == 0) {
                float2 t = st.a[m];
                st.a[m] = st.a[m | tb];
                st.a[m | tb] = t;
            }
        }
    }
}

template<int J>
__device__ __forceinline__ void ansatzStep(St& st, const float* cw, const float* sw, int lane) {
    constexpr int C = (J < 7) ? J : 0;
    constexpr int T = (J < 7) ? J + 1 : 7;
    float c = cw[J], s = sw[J];
    gateRX<J>(st, c, s, lane);
    cnot<C, T>(st, lane);
    gateRY<J>(st, c, s, lane);
    cnot<C, T>(st, lane);
    gateRZ<J>(st, c, s, lane);
}

__device__ __forceinline__ void ansatz(St& st, const float* cw, const float* sw, int lane) {
    ansatzStep<0>(st, cw, sw, lane);
    ansatzStep<1>(st, cw, sw, lane);
    ansatzStep<2>(st, cw, sw, lane);
    ansatzStep<3>(st, cw, sw, lane);
    ansatzStep<4>(st, cw, sw, lane);
    ansatzStep<5>(st, cw, sw, lane);
    ansatzStep<6>(st, cw, sw, lane);
    ansatzStep<7>(st, cw, sw, lane);
}

// ---------------- precompute 1: weight trig + psi0 (1 warp) -----------------
__global__ void precompute_kernel(const float* __restrict__ weights) {
    int lane = threadIdx.x;
    if (lane < 24) {
        const float TWO_PI = 6.28318530717958647692f;
        float w = weights[lane];
        float wm = fmodf(w, TWO_PI);
        if (wm < 0.f) wm += TWO_PI;
        g_cosw[lane] = cosf(0.5f * wm);
        g_sinw[lane] = sinf(0.5f * wm);
    }
    __syncwarp();
    St st;
#pragma unroll
    for (int m = 0; m < 8; ++m) st.a[m] = make_float2(0.f, 0.f);
    if (lane == 0) st.a[0] = make_float2(1.f, 0.f);
    ansatz(st, &g_cosw[0], &g_sinw[0], lane);
#pragma unroll
    for (int m = 0; m < 8; ++m) g_psi0[(lane << 3) | m] = st.a[m];
}

// ---------------- precompute 2: 81 grid circuit evaluations -----------------
// angles a_i in {0, pi/2, pi} -> (cos(a/2), sin(a/2)) in {(1,0),(r,r),(0,1)}
__global__ void gridsim_kernel() {
    const float GC[3] = {1.f, 0.70710678118654752440f, 0.f};
    const float GS[3] = {0.f, 0.70710678118654752440f, 1.f};
    int lane = threadIdx.x;
    int n = blockIdx.x;            // 0..80
    int k0 = n / 27, k1 = (n / 9) % 3, k2 = (n / 3) % 3, k3 = n % 3;

    St st;
#pragma unroll
    for (int m = 0; m < 8; ++m) st.a[m] = g_psi0[(lane << 3) | m];

    gateRY<0>(st, GC[k0], GS[k0], lane);
    gateRY<1>(st, GC[k1], GS[k1], lane);
    gateRY<2>(st, GC[k2], GS[k2], lane);
    gateRY<3>(st, GC[k3], GS[k3], lane);

    ansatz(st, &g_cosw[8],  &g_sinw[8],  lane);
    ansatz(st, &g_cosw[16], &g_sinw[16], lane);

    float vj[8];
#pragma unroll
    for (int j = 0; j < 8; ++j) vj[j] = 0.f;
#pragma unroll
    for (int m = 0; m < 8; ++m) {
        float2 a = st.a[m];
        float p = a.x * a.x + a.y * a.y;
        int idx = (lane << 3) | m;
#pragma unroll
        for (int j = 0; j < 8; ++j) vj[j] += ((idx >> (7 - j)) & 1) ? -p : p;
    }
#pragma unroll
    for (int j = 0; j < 8; ++j) {
        float v = vj[j];
#pragma unroll
        for (int o = 16; o; o >>= 1) v += __shfl_xor_sync(FULL, v, o);
        if (lane == 0) g_F[n * 8 + j] = v;
    }
}

// ---------------- precompute 3: grid values -> trig-poly coefficients -------
// per axis: f0=f(0), f1=f(pi/2), f2=f(pi) over basis {1, cos, sin}:
//   c_const=(f0+f2)/2 ; c_cos=(f0-f2)/2 ; c_sin=f1-c_const
__global__ void transform_kernel(const float* __restrict__ db, float* __restrict__ out) {
    int t = threadIdx.x;
    if (t < 8) {
        float buf[81];
        for (int n = 0; n < 81; ++n) buf[n] = g_F[n * 8 + t];
        const int strides[4] = {27, 9, 3, 1};
        for (int a = 0; a < 4; ++a) {
            int st = strides[a];
            for (int n = 0; n < 81; ++n) {
                if ((n / st) % 3 == 0) {
                    float f0 = buf[n], f1 = buf[n + st], f2 = buf[n + 2 * st];
                    float kc = 0.5f * (f0 + f2);
                    buf[n]          = kc;
                    buf[n + st]     = 0.5f * (f0 - f2);
                    buf[n + 2 * st] = f1 - kc;
                }
            }
        }
        for (int n = 0; n < 81; ++n) g_coef[t * 81 + n] = buf[n];
    }
    // init output with bias (graph replays re-init every time)
    if (t >= 32 && t < 64) out[t - 32] = db[0];
}

// ---------------- polynomial evaluation helpers ------------------------------
__device__ __forceinline__ void build_t9(const float* a, float* t01, float* t23) {
    float c[4], s[4];
#pragma unroll
    for (int i = 0; i < 4; ++i) sincosf(a[i], &s[i], &c[i]);
    float t0[3] = {1.f, c[0], s[0]};
    float t1[3] = {1.f, c[1], s[1]};
    float t2[3] = {1.f, c[2], s[2]};
    float t3[3] = {1.f, c[3], s[3]};
#pragma unroll
    for (int i = 0; i < 3; ++i)
#pragma unroll
        for (int j = 0; j < 3; ++j) {
            t01[i * 3 + j] = t0[i] * t1[j];
            t23[i * 3 + j] = t2[i] * t3[j];
        }
}

__device__ __forceinline__ float eval81(const float* __restrict__ sc,
                                        const float* t01, const float* t23) {
    float acc = 0.f;
#pragma unroll
    for (int i = 0; i < 9; ++i) {
        float p = 0.f;
#pragma unroll
        for (int l = 0; l < 9; ++l) p = fmaf(sc[i * 9 + l], t23[l], p);
        acc = fmaf(t01[i], p, acc);
    }
    return acc;
}

// ---------------- layer 1: relu(<Z_0>) per window ----------------------------
__global__ void __launch_bounds__(256) layer1_kernel(const float* __restrict__ x) {
    __shared__ float sc[81];
    if (threadIdx.x < 81) sc[threadIdx.x] = g_coef[threadIdx.x];
    __syncthreads();

    int b = blockIdx.y;
    int s = blockIdx.x * 256 + threadIdx.x;
    if (s >= 1023) return;

    float a[4];
#pragma unroll
    for (int i = 0; i < 4; ++i) {
        int l = s - 1 + i;
        a[i] = (l >= 0 && l < 1024) ? x[b * 1024 + l] : 0.f;
    }
    float t01[9], t23[9];
    build_t9(a, t01, t23);
    float v = eval81(sc, t01, t23);
    g_a1[b * 1023 + s] = fmaxf(v, 0.f);
}

// ---------------- layer 2 + maxpool + dense (fused) --------------------------
__global__ void __launch_bounds__(256) layer2_kernel(const float* __restrict__ dw,
                                                     float* __restrict__ out) {
    __shared__ float sc[648];
    __shared__ float red[256];
    for (int i = threadIdx.x; i < 648; i += 256) sc[i] = g_coef[i];
    __syncthreads();

    int b = blockIdx.y;
    int s = blockIdx.x * 256 + threadIdx.x;
    float contrib = 0.f;
    if (s < 1022) {
        float a[4];
#pragma unroll
        for (int i = 0; i < 4; ++i) {
            int l = s - 1 + i;
            a[i] = (l >= 0 && l < 1023) ? g_a1[b * 1023 + l] : 0.f;
        }
        float t01[9], t23[9];
        build_t9(a, t01, t23);
        float best = -1e30f;
#pragma unroll
        for (int j = 0; j < 8; ++j)
            best = fmaxf(best, eval81(&sc[j * 81], t01, t23));
        // max_j relu(v_j) == relu(max_j v_j)
        contrib = fmaxf(best, 0.f) * dw[s];
    }
    red[threadIdx.x] = contrib;
    __syncthreads();
#pragma unroll
    for (int o = 128; o; o >>= 1) {
        if (threadIdx.x < o) red[threadIdx.x] += red[threadIdx.x + o];
        __syncthreads();
    }
    if (threadIdx.x == 0) atomicAdd(&out[b], red[0]);
}

// ---------------- launch ------------------------------------------------------
extern "C" void kernel_launch(void* const* d_in, const int* in_sizes, int n_in,
                              void* d_out, int out_size) {
    const float* x       = (const float*)d_in[0];   // (32,1024,1)
    const float* weights = (const float*)d_in[1];   // (3,8)
    const float* dw      = (const float*)d_in[2];   // (1022,1)
    const float* db      = (const float*)d_in[3];   // (1,)
    float* out = (float*)d_out;                     // (32,1)

    precompute_kernel<<<1, 32>>>(weights);
    gridsim_kernel<<<81, 32>>>();
    transform_kernel<<<1, 64>>>(db, out);

    dim3 g1(4, 32);   // 4*256 >= 1023 positions, 32 batches
    layer1_kernel<<<g1, 256>>>(x);
    dim3 g2(4, 32);   // 4*256 >= 1022 positions
    layer2_kernel<<<g2, 256>>>(dw, out);
}

// round 3
// speedup vs baseline: 15.3521x; 2.0078x over previous
#include <cuda_runtime.h>

#define FULL 0xffffffffu

// ---------------- scratch ----------------------------------------------------
__device__ float g_F[81 * 8];     // grid evaluations of <Z_j>, layout [n][j]

// ---------------- warp statevector simulation (gridsim only) ----------------
struct St { float2 a[8]; };

__device__ __forceinline__ float2 shxor(float2 v, int m) {
    float2 r;
    r.x = __shfl_xor_sync(FULL, v.x, m);
    r.y = __shfl_xor_sync(FULL, v.y, m);
    return r;
}

template<int Q>
__device__ __forceinline__ void gateRY(St& st, float c, float s, int lane) {
    if constexpr (Q >= 5) {
        constexpr int bit = 1 << (7 - Q);
#pragma unroll
        for (int m = 0; m < 8; ++m) {
            if ((m & bit) == 0) {
                float2 a = st.a[m], b = st.a[m | bit];
                st.a[m]       = make_float2(c * a.x - s * b.x, c * a.y - s * b.y);
                st.a[m | bit] = make_float2(s * a.x + c * b.x, s * a.y + c * b.y);
            }
        }
    } else {
        constexpr int lm = 1 << (4 - Q);
        float sg = (lane & lm) ? s : -s;
#pragma unroll
        for (int m = 0; m < 8; ++m) {
            float2 o = shxor(st.a[m], lm);
            float2 a = st.a[m];
            st.a[m] = make_float2(c * a.x + sg * o.x, c * a.y + sg * o.y);
        }
    }
}

template<int Q>
__device__ __forceinline__ void gateRX(St& st, float c, float s, int lane) {
    if constexpr (Q >= 5) {
        constexpr int bit = 1 << (7 - Q);
#pragma unroll
        for (int m = 0; m < 8; ++m) {
            if ((m & bit) == 0) {
                float2 a = st.a[m], b = st.a[m | bit];
                st.a[m]       = make_float2(c * a.x + s * b.y, c * a.y - s * b.x);
                st.a[m | bit] = make_float2(c * b.x + s * a.y, c * b.y - s * a.x);
            }
        }
    } else {
        constexpr int lm = 1 << (4 - Q);
#pragma unroll
        for (int m = 0; m < 8; ++m) {
            float2 o = shxor(st.a[m], lm);
            float2 a = st.a[m];
            st.a[m] = make_float2(c * a.x + s * o.y, c * a.y - s * o.x);
        }
    }
}

template<int Q>
__device__ __forceinline__ void gateRZ(St& st, float c, float s, int lane) {
    if constexpr (Q >= 5) {
        constexpr int bit = 1 << (7 - Q);
#pragma unroll
        for (int m = 0; m < 8; ++m) {
            float f = (m & bit) ? s : -s;
            float2 a = st.a[m];
            st.a[m] = make_float2(c * a.x - f * a.y, c * a.y + f * a.x);
        }
    } else {
        constexpr int lm = 1 << (4 - Q);
        float f = (lane & lm) ? s : -s;
#pragma unroll
        for (int m = 0; m < 8; ++m) {
            float2 a = st.a[m];
            st.a[m] = make_float2(c * a.x - f * a.y, c * a.y + f * a.x);
        }
    }
}

template<int C, int T>
__device__ __forceinline__ void cnot(St& st, int lane) {
    if constexpr (C <= 4 && T <= 4) {
        constexpr int cm = 1 << (4 - C);
        constexpr int tm = 1 << (4 - T);
        bool ctrl = (lane & cm) != 0;
#pragma unroll
        for (int m = 0; m < 8; ++m) {
            float2 o = shxor(st.a[m], tm);
            if (ctrl) st.a[m] = o;
        }
    } else if constexpr (C <= 4 && T >= 5) {
        constexpr int cm = 1 << (4 - C);
        constexpr int tb = 1 << (7 - T);
        bool ctrl = (lane & cm) != 0;
#pragma unroll
        for (int m = 0; m < 8; ++m) {
            if ((m & tb) == 0) {
                float2 a = st.a[m], b = st.a[m | tb];
                st.a[m]      = ctrl ? b : a;
                st.a[m | tb] = ctrl ? a : b;
            }
        }
    } else {
        constexpr int cb = 1 << (7 - C);
        constexpr int tb = 1 << (7 - T);
#pragma unroll
        for (int m = 0; m < 8; ++m) {
            if ((m & cb) != 0 && (m & tb) == 0) {
                float2 t = st.a[m];
                st.a[m] = st.a[m | tb];
                st.a[m | tb] = t;
            }
        }
    }
}

template<int J>
__device__ __forceinline__ void ansatzStep(St& st, const float* cw, const float* sw, int lane) {
    constexpr int C = (J < 7) ? J : 0;
    constexpr int T = (J < 7) ? J + 1 : 7;
    float c = cw[J], s = sw[J];
    gateRX<J>(st, c, s, lane);
    cnot<C, T>(st, lane);
    gateRY<J>(st, c, s, lane);
    cnot<C, T>(st, lane);
    gateRZ<J>(st, c, s, lane);
}

__device__ __forceinline__ void ansatz(St& st, const float* cw, const float* sw, int lane) {
    ansatzStep<0>(st, cw, sw, lane);
    ansatzStep<1>(st, cw, sw, lane);
    ansatzStep<2>(st, cw, sw, lane);
    ansatzStep<3>(st, cw, sw, lane);
    ansatzStep<4>(st, cw, sw, lane);
    ansatzStep<5>(st, cw, sw, lane);
    ansatzStep<6>(st, cw, sw, lane);
    ansatzStep<7>(st, cw, sw, lane);
}

// ---------------- kernel 1: 81 grid circuits (each block self-contained) ----
__global__ void gridsim_kernel(const float* __restrict__ weights,
                               const float* __restrict__ db,
                               float* __restrict__ out) {
    __shared__ float cw[24], sw[24];
    int lane = threadIdx.x;

    // block 0 seeds the output with the bias (runs before fused's atomics)
    if (blockIdx.x == 0) out[lane] = db[0];

    if (lane < 24) {
        const float TWO_PI = 6.28318530717958647692f;
        float w = weights[lane];
        float wm = fmodf(w, TWO_PI);
        if (wm < 0.f) wm += TWO_PI;
        cw[lane] = cosf(0.5f * wm);
        sw[lane] = sinf(0.5f * wm);
    }
    __syncwarp();

    // psi0 = ansatz(|0>, w[0])
    St st;
#pragma unroll
    for (int m = 0; m < 8; ++m) st.a[m] = make_float2(0.f, 0.f);
    if (lane == 0) st.a[0] = make_float2(1.f, 0.f);
    ansatz(st, &cw[0], &sw[0], lane);

    // data RYs at grid angles {0, pi/2, pi}
    const float GC[3] = {1.f, 0.70710678118654752440f, 0.f};
    const float GS[3] = {0.f, 0.70710678118654752440f, 1.f};
    int n = blockIdx.x;
    int k0 = n / 27, k1 = (n / 9) % 3, k2 = (n / 3) % 3, k3 = n % 3;
    gateRY<0>(st, GC[k0], GS[k0], lane);
    gateRY<1>(st, GC[k1], GS[k1], lane);
    gateRY<2>(st, GC[k2], GS[k2], lane);
    gateRY<3>(st, GC[k3], GS[k3], lane);

    ansatz(st, &cw[8],  &sw[8],  lane);
    ansatz(st, &cw[16], &sw[16], lane);

    float vj[8];
#pragma unroll
    for (int j = 0; j < 8; ++j) vj[j] = 0.f;
#pragma unroll
    for (int m = 0; m < 8; ++m) {
        float2 a = st.a[m];
        float p = a.x * a.x + a.y * a.y;
        int idx = (lane << 3) | m;
#pragma unroll
        for (int j = 0; j < 8; ++j) vj[j] += ((idx >> (7 - j)) & 1) ? -p : p;
    }
#pragma unroll
    for (int j = 0; j < 8; ++j) {
        float v = vj[j];
#pragma unroll
        for (int o = 16; o; o >>= 1) v += __shfl_xor_sync(FULL, v, o);
        if (lane == 0) g_F[n * 8 + j] = v;
    }
}

// ---------------- kernel 2: transform + layer1 + layer2 + pool + dense ------
// grid (8, 32), 128 threads. Chunk of CH=128 layer-2 positions per block.
#define CH 128
#define NP (CH + 3)    // layer-1 values needed (halo)
#define NX (CH + 6)    // x sincos values needed

__device__ __forceinline__ float eval81(const float* __restrict__ sc,
                                        const float* t01, const float* t23) {
    float acc = 0.f;
#pragma unroll
    for (int i = 0; i < 9; ++i) {
        float p = 0.f;
#pragma unroll
        for (int l = 0; l < 9; ++l) p = fmaf(sc[i * 9 + l], t23[l], p);
        acc = fmaf(t01[i], p, acc);
    }
    return acc;
}

__device__ __forceinline__ void build_t9(float c0, float s0, float c1, float s1,
                                         float c2, float s2, float c3, float s3,
                                         float* t01, float* t23) {
    float t0[3] = {1.f, c0, s0};
    float t1[3] = {1.f, c1, s1};
    float t2[3] = {1.f, c2, s2};
    float t3[3] = {1.f, c3, s3};
#pragma unroll
    for (int i = 0; i < 3; ++i)
#pragma unroll
        for (int j = 0; j < 3; ++j) {
            t01[i * 3 + j] = t0[i] * t1[j];
            t23[i * 3 + j] = t2[i] * t3[j];
        }
}

__global__ void __launch_bounds__(128) fused_kernel(const float* __restrict__ x,
                                                    const float* __restrict__ dw,
                                                    float* __restrict__ out) {
    __shared__ float coef[648];          // [j][81], transformed in place
    __shared__ float xc[NX], xs[NX];     // sincos of input window
    __shared__ float ac[NP], as_[NP];    // sincos of layer-1 relu values
    __shared__ float red[128];

    int t = threadIdx.x;
    int b = blockIdx.y;
    int s0 = blockIdx.x * CH;

    // --- load F transposed: coef[j*81+n] = g_F[n*8+j] ---
    for (int i = t; i < 648; i += 128) {
        int j = i / 81, n = i - j * 81;
        coef[i] = g_F[n * 8 + j];
    }
    // --- sincos of x window: x index l = s0-2+k ---
    for (int k = t; k < NX; k += 128) {
        int l = s0 - 2 + k;
        float cv = 1.f, sv = 0.f;
        if (l >= 0 && l < 1024) {
            float ang = x[b * 1024 + l];
            __sincosf(ang, &sv, &cv);
        }
        xc[k] = cv; xs[k] = sv;
    }
    __syncthreads();

    // --- transform: per axis {1,cos,sin} coefficient extraction, in place ---
    // pass strides 27, 9, 3, 1; 8 channels x 27 triads = 216 per pass
#pragma unroll
    for (int a = 0; a < 4; ++a) {
        const int stv = (a == 0) ? 27 : (a == 1) ? 9 : (a == 2) ? 3 : 1;
        for (int i = t; i < 216; i += 128) {
            int j = i / 27, r = i - j * 27;
            int base = j * 81 + (r / stv) * (3 * stv) + (r % stv);
            float f0 = coef[base], f1 = coef[base + stv], f2 = coef[base + 2 * stv];
            float kc = 0.5f * (f0 + f2);
            coef[base]           = kc;
            coef[base + stv]     = 0.5f * (f0 - f2);
            coef[base + 2 * stv] = f1 - kc;
        }
        __syncthreads();
    }

    // --- layer 1: value at position p = s0-1+k, k in [0, NP) ---
    for (int k = t; k < NP; k += 128) {
        int p = s0 - 1 + k;
        float cv = 1.f, sv = 0.f;          // OOB position -> angle 0
        if (p >= 0 && p < 1023) {
            float t01[9], t23[9];
            build_t9(xc[k], xs[k], xc[k + 1], xs[k + 1],
                     xc[k + 2], xs[k + 2], xc[k + 3], xs[k + 3], t01, t23);
            float v = eval81(&coef[0], t01, t23);
            v = fmaxf(v, 0.f);
            __sincosf(v, &sv, &cv);
        }
        ac[k] = cv; as_[k] = sv;
    }
    __syncthreads();

    // --- layer 2 + channel max + relu + dense contribution ---
    int s = s0 + t;
    float contrib = 0.f;
    if (s < 1022) {
        float t01[9], t23[9];
        build_t9(ac[t], as_[t], ac[t + 1], as_[t + 1],
                 ac[t + 2], as_[t + 2], ac[t + 3], as_[t + 3], t01, t23);
        float best = -1e30f;
#pragma unroll
        for (int j = 0; j < 8; ++j)
            best = fmaxf(best, eval81(&coef[j * 81], t01, t23));
        contrib = fmaxf(best, 0.f) * dw[s];   // max relu == relu max
    }

    // --- block reduce + atomic ---
    red[t] = contrib;
    __syncthreads();
#pragma unroll
    for (int o = 64; o >= 32; o >>= 1) {
        if (t < o) red[t] += red[t + o];
        __syncthreads();
    }
    if (t < 32) {
        float v = red[t];
#pragma unroll
        for (int o = 16; o; o >>= 1) v += __shfl_xor_sync(FULL, v, o);
        if (t == 0) atomicAdd(&out[b], v);
    }
}

// ---------------- launch ------------------------------------------------------
extern "C" void kernel_launch(void* const* d_in, const int* in_sizes, int n_in,
                              void* d_out, int out_size) {
    const float* x       = (const float*)d_in[0];   // (32,1024,1)
    const float* weights = (const float*)d_in[1];   // (3,8)
    const float* dw      = (const float*)d_in[2];   // (1022,1)
    const float* db      = (const float*)d_in[3];   // (1,)
    float* out = (float*)d_out;                     // (32,1)

    gridsim_kernel<<<81, 32>>>(weights, db, out);
    dim3 g((1022 + CH - 1) / CH, 32);               // (8, 32)
    fused_kernel<<<g, 128>>>(x, dw, out);
}